// round 6
// baseline (speedup 1.0000x reference)
#include <cuda_runtime.h>
#include <cstdint>
#include <math.h>

// ---------------------------------------------------------------------------
// Single persistent kernel.
// theta_i = mean of x[b,0, 0:6, 6i:6i+6]; z_i = cos(lam)cos(th)+sin(lam)sin(phi)sin(th)
// out[b] = [z0, z0z1, z0z1z2, z0z1z2z3]  -> BatchNorm1d (batch stats, fp32)
// ---------------------------------------------------------------------------

#define B_TOTAL  65536
#define IPB      32                     // images per tile
#define GRID     256                    // persistent blocks (co-resident)
#define TPB      (B_TOTAL / (IPB * GRID))   // 8 tiles per block
#define THREADS  256
#define SROW     148                    // padded smem row (floats)

__device__ __align__(16) float g_part[GRID * 8];
__device__ unsigned g_cnt = 0;
__device__ unsigned g_epoch = 0;

__device__ __forceinline__ void cp16(unsigned int saddr, const float4* gptr) {
    asm volatile("cp.async.cg.shared.global [%0], [%1], 16;" :: "r"(saddr), "l"(gptr));
}

__global__ __launch_bounds__(THREADS)
void qfc_persistent(const float* __restrict__ x,
                    const float* __restrict__ pr,
                    const float* __restrict__ gamma,
                    const float* __restrict__ beta,
                    float* __restrict__ out)
{
    __shared__ __align__(16) float  sd[2][IPB][SROW];   // double-buffered tiles
    __shared__ float  sz[IPB][4];
    __shared__ __align__(16) float4 s_out[TPB * IPB];   // raw outputs stash (256)
    __shared__ float  swarp[8][8];
    __shared__ float  sb[8];

    const int tid = threadIdx.x;
    const float4* __restrict__ x4 = (const float4*)x;
    const int tile0 = blockIdx.x * TPB;

    // cp.async staging of one tile into buffer b
    auto stage = [&](int t, int b) {
        const int ib = (tile0 + t) * IPB;
#pragma unroll
        for (int it = 0; it < 5; it++) {
            int i = tid + it * THREADS;
            if (i < IPB * 36) {
                int img = i / 36;
                int p   = i - img * 36;
                unsigned int sa =
                    (unsigned int)__cvta_generic_to_shared(&sd[b][img][p * 4]);
                cp16(sa, &x4[(ib + img) * 144 + p]);
            }
        }
        asm volatile("cp.async.commit_group;");
    };

    stage(0, 0);

    const int g = tid & 3;
    const float phi  = pr[g * 2 + 0];
    const float lam  = pr[g * 2 + 1];
    const float clam = __cosf(lam);
    const float k2   = __sinf(lam) * __sinf(phi);

    float acc[8];
#pragma unroll
    for (int k = 0; k < 8; k++) acc[k] = 0.f;

    // ---- Phase 1: pipelined tiles --------------------------------------
#pragma unroll
    for (int t = 0; t < TPB; t++) {
        if (t + 1 < TPB) {
            stage(t + 1, (t + 1) & 1);
            asm volatile("cp.async.wait_group 1;");
        } else {
            asm volatile("cp.async.wait_group 0;");
        }
        __syncthreads();

        const int b = t & 1;
        if (tid < IPB * 4) {
            const int img = tid >> 2;
            const float* row = &sd[b][img][g * 6];
            float a0 = 0.f, a1 = 0.f, a2 = 0.f, a3 = 0.f;
#pragma unroll
            for (int r = 0; r < 6; r++) {
                a0 += row[r * 24 + 0];
                a1 += row[r * 24 + 1];
                a2 += row[r * 24 + 2];
                a3 += row[r * 24 + 3];
                a0 += row[r * 24 + 4];
                a1 += row[r * 24 + 5];
            }
            const float theta = ((a0 + a1) + (a2 + a3)) * (1.f / 36.f);
            float st, ct;
            __sincosf(theta, &st, &ct);
            sz[img][g] = clam * ct + k2 * st;
        }
        __syncthreads();

        if (tid < IPB) {
            float4 zz = *(float4*)&sz[tid][0];
            float o0 = zz.x;
            float o1 = o0 * zz.y;
            float o2 = o1 * zz.z;
            float o3 = o2 * zz.w;
            s_out[t * IPB + tid] = make_float4(o0, o1, o2, o3);
            acc[0] += o0;      acc[1] += o1;      acc[2] += o2;      acc[3] += o3;
            acc[4] += o0 * o0; acc[5] += o1 * o1; acc[6] += o2 * o2; acc[7] += o3 * o3;
        }
        __syncthreads();
    }

    // per-block deterministic reduction -> g_part
    if (tid < 32) {
#pragma unroll
        for (int k = 0; k < 8; k++) {
#pragma unroll
            for (int off = 16; off; off >>= 1)
                acc[k] += __shfl_down_sync(0xffffffffu, acc[k], off);
        }
        if (tid == 0) {
            *(float4*)&g_part[blockIdx.x * 8]     = make_float4(acc[0], acc[1], acc[2], acc[3]);
            *(float4*)&g_part[blockIdx.x * 8 + 4] = make_float4(acc[4], acc[5], acc[6], acc[7]);
        }
    }

    // ---- Grid barrier (epoch-based, replay-safe, deterministic) --------
    __syncthreads();
    if (tid == 0) {
        unsigned e = *(volatile unsigned*)&g_epoch;
        __threadfence();                       // publish g_part
        unsigned old = atomicAdd(&g_cnt, 1);
        if (old == GRID - 1) {
            g_cnt = 0;
            __threadfence();
            atomicAdd(&g_epoch, 1);            // release
        } else {
            while (*(volatile unsigned*)&g_epoch == e) { }
        }
        __threadfence();                       // acquire
    }
    __syncthreads();

    // ---- Phase 2: stats (redundant per block, deterministic) -----------
    {
        const int wrp  = tid >> 5;
        const int lane = tid & 31;
        const float4* p4 = (const float4*)g_part;        // 512 float4
        float4 s = __ldcg(&p4[tid * 2]);
        float4 q = __ldcg(&p4[tid * 2 + 1]);
        float r[8] = {s.x, s.y, s.z, s.w, q.x, q.y, q.z, q.w};
#pragma unroll
        for (int k = 0; k < 8; k++) {
#pragma unroll
            for (int off = 16; off; off >>= 1)
                r[k] += __shfl_down_sync(0xffffffffu, r[k], off);
        }
        if (lane == 0) {
#pragma unroll
            for (int k = 0; k < 8; k++) swarp[wrp][k] = r[k];
        }
        __syncthreads();
        if (tid < 4) {
            float ss = 0.f, qq = 0.f;
#pragma unroll
            for (int w = 0; w < 8; w++) { ss += swarp[w][tid]; qq += swarp[w][4 + tid]; }
            const float mean = ss * (1.f / (float)B_TOTAL);
            const float ex2  = qq * (1.f / (float)B_TOTAL);
            const float var  = fmaxf(ex2 - mean * mean, 0.f);
            const float inv  = rsqrtf(var + 1e-5f);
            const float sc   = gamma[tid] * inv;
            sb[tid]     = sc;
            sb[4 + tid] = beta[tid] - mean * sc;
        }
        __syncthreads();
    }

    // ---- Phase 3: normalize from smem stash, single gmem write ---------
    {
        const float4 scv = *(const float4*)&sb[0];
        const float4 biv = *(const float4*)&sb[4];
        float4 v = s_out[tid];
        v.x = v.x * scv.x + biv.x;
        v.y = v.y * scv.y + biv.y;
        v.z = v.z * scv.z + biv.z;
        v.w = v.w * scv.w + biv.w;
        ((float4*)out)[blockIdx.x * (TPB * IPB) + tid] = v;
    }
}

extern "C" void kernel_launch(void* const* d_in, const int* in_sizes, int n_in,
                              void* d_out, int out_size)
{
    const float* x      = (const float*)d_in[0];   // [65536,1,24,24]
    const float* params = (const float*)d_in[1];   // [4,2]
    const float* gamma  = (const float*)d_in[2];   // [4]
    const float* beta   = (const float*)d_in[3];   // [4]
    float* out = (float*)d_out;                    // [65536,4]

    qfc_persistent<<<GRID, THREADS>>>(x, params, gamma, beta, out);
}